// round 2
// baseline (speedup 1.0000x reference)
#include <cuda_runtime.h>
#include <cuda_bf16.h>

// Problem constants
#define B_   64
#define C_   2048
#define HW_  576
#define NCHUNK 4
#define CPC  (C_ / NCHUNK)   // 512 channels per chunk

// Scratch (allocation-free rule: __device__ globals)
__device__ float  g_part[2][B_][NCHUNK][HW_];   // per-chunk partial lum
__device__ float  g_lum_v[B_][HW_];             // lum_v row-major
__device__ float  g_lum_iT[HW_][B_];            // lum_i TRANSPOSED for coalesced j-reads
__device__ double g_sum;                        // masked mse accumulator

// ---------------------------------------------------------------------------
// Kernel 1: streaming sum-of-squares over channels. Thread = pixel p.
// Warp reads 32 consecutive floats per channel step -> fully coalesced.
// grid = (NCHUNK, B, 2), block = 576
// ---------------------------------------------------------------------------
__global__ void k_lum_partial(const float* __restrict__ fv,
                              const float* __restrict__ fi) {
    const int chunk = blockIdx.x;
    const int b     = blockIdx.y;
    const int t     = blockIdx.z;
    const int p     = threadIdx.x;              // 0..575

    const float* __restrict__ f = (t == 0) ? fv : fi;
    const float* __restrict__ base =
        f + ((size_t)b * C_ + (size_t)chunk * CPC) * HW_ + p;

    float acc = 0.0f;
#pragma unroll 8
    for (int c = 0; c < CPC; ++c) {
        float x = base[(size_t)c * HW_];
        acc = fmaf(x, x, acc);
    }
    g_part[t][b][chunk][p] = acc;
}

// ---------------------------------------------------------------------------
// Kernel 2: fold partial chunks; lum_v row-major, lum_i transposed.
// Also zeroes g_sum (stream-ordered before k_pair).
// grid = (B, 2), block = 576
// ---------------------------------------------------------------------------
__global__ void k_lum_reduce() {
    const int b = blockIdx.x;
    const int t = blockIdx.y;
    const int p = threadIdx.x;

    if (b == 0 && t == 0 && p == 0) g_sum = 0.0;

    float s = g_part[t][b][0][p] + g_part[t][b][1][p]
            + g_part[t][b][2][p] + g_part[t][b][3][p];

    if (t == 0) g_lum_v[b][p]  = s;
    else        g_lum_iT[p][b] = s;
}

// ---------------------------------------------------------------------------
// Kernel 3: pairwise MSE + mask + reduce. block = i, thread = j.
// mse_sum(i,j) = sv2 + si2 - 2*cross  (all p-sums), mse = mse_sum / HW.
// fp32 inner chunks (32 terms) flushed to double accumulators.
// grid = 64, block = 64
// NOTE: labels are int32 — JAX default config disables x64, so the
// reference's jnp.int64 request silently produces int32.
// ---------------------------------------------------------------------------
__global__ void k_pair(const int* __restrict__ labels) {
    const int i = blockIdx.x;
    const int j = threadIdx.x;   // 0..63

    __shared__ float  s_lv[HW_];
    __shared__ double s_red[64];

    // cooperative load of lum_v[i] (coalesced)
    for (int p = j; p < HW_; p += 64) s_lv[p] = g_lum_v[i][p];
    __syncthreads();

    // sv2 = sum_p lv^2  (per-thread fp32 partial of 9 terms -> double reduce)
    {
        float pv = 0.0f;
        for (int p = j; p < HW_; p += 64) {
            float v = s_lv[p];
            pv = fmaf(v, v, pv);
        }
        s_red[j] = (double)pv;
    }
    __syncthreads();
    for (int s = 32; s > 0; s >>= 1) {
        if (j < s) s_red[j] += s_red[j + s];
        __syncthreads();
    }
    const double sv2 = s_red[0];
    __syncthreads();

    // cross = sum_p lv*li,  si2 = sum_p li^2   (li reads warp-coalesced via transpose)
    double crossd = 0.0, si2d = 0.0;
    for (int p0 = 0; p0 < HW_; p0 += 32) {
        float cf = 0.0f, sf = 0.0f;
#pragma unroll
        for (int k = 0; k < 32; ++k) {
            int   p  = p0 + k;
            float lv = s_lv[p];
            float li = g_lum_iT[p][j];
            cf = fmaf(lv, li, cf);
            sf = fmaf(li, li, sf);
        }
        crossd += (double)cf;
        si2d   += (double)sf;
    }

    const double mse = (sv2 + si2d - 2.0 * crossd) / (double)HW_;

    const int Li = labels[i];
    const int Lj = labels[j];
    const bool m = (Li == Lj) && (i != j);

    s_red[j] = m ? mse : 0.0;
    __syncthreads();
    for (int s = 32; s > 0; s >>= 1) {
        if (j < s) s_red[j] += s_red[j + s];
        __syncthreads();
    }
    if (j == 0) atomicAdd(&g_sum, s_red[0]);
}

// ---------------------------------------------------------------------------
// Kernel 4: final scalar. Count pairs from labels (deterministic), divide.
// ---------------------------------------------------------------------------
__global__ void k_final(const int* __restrict__ labels,
                        float* __restrict__ out) {
    int lab[B_];
    for (int a = 0; a < B_; ++a) lab[a] = labels[a];
    int cnt = 0;
    for (int a = 0; a < B_; ++a)
        for (int b = 0; b < B_; ++b)
            if (a != b && lab[a] == lab[b]) ++cnt;
    out[0] = (cnt > 0) ? (float)(g_sum / (double)cnt) : 0.0f;
}

extern "C" void kernel_launch(void* const* d_in, const int* in_sizes, int n_in,
                              void* d_out, int out_size) {
    const float* fv     = (const float*)d_in[0];
    const float* fi     = (const float*)d_in[1];
    const int*   labels = (const int*)d_in[2];
    float*       out    = (float*)d_out;

    k_lum_partial<<<dim3(NCHUNK, B_, 2), HW_>>>(fv, fi);
    k_lum_reduce<<<dim3(B_, 2), HW_>>>();
    k_pair<<<B_, 64>>>(labels);
    k_final<<<1, 1>>>(labels, out);
}

// round 3
// speedup vs baseline: 1.3983x; 1.3983x over previous
#include <cuda_runtime.h>
#include <cuda_bf16.h>

// Problem constants
#define B_   64
#define C_   2048
#define HW_  576
#define NCHUNK 16
#define CPC  (C_ / NCHUNK)   // 128 channels per chunk

// Scratch (allocation-free rule: __device__ globals)
__device__ float        g_part[2][B_][NCHUNK][HW_]; // per-chunk partial lum
__device__ float        g_lum_v[B_][HW_];           // lum_v row-major
__device__ float        g_lum_iT[HW_][B_];          // lum_i TRANSPOSED
__device__ double       g_sum;                      // masked mse accumulator
__device__ int          g_cnt;                      // masked pair count
__device__ unsigned int g_ticket;                   // last-block election (static-init 0)

// ---------------------------------------------------------------------------
// Kernel 1: streaming sum-of-squares over channels. Thread = pixel p.
// Warp reads 32 consecutive floats per channel step -> fully coalesced.
// grid = (NCHUNK, B, 2), block = 576. unroll 16 => 16 loads in flight/thread.
// ---------------------------------------------------------------------------
__global__ void k_lum_partial(const float* __restrict__ fv,
                              const float* __restrict__ fi) {
    const int chunk = blockIdx.x;
    const int b     = blockIdx.y;
    const int t     = blockIdx.z;
    const int p     = threadIdx.x;              // 0..575

    const float* __restrict__ f = (t == 0) ? fv : fi;
    const float* __restrict__ base =
        f + ((size_t)b * C_ + (size_t)chunk * CPC) * HW_ + p;

    float acc = 0.0f;
#pragma unroll 16
    for (int c = 0; c < CPC; ++c) {
        float x = base[(size_t)c * HW_];
        acc = fmaf(x, x, acc);
    }
    g_part[t][b][chunk][p] = acc;
}

// ---------------------------------------------------------------------------
// Kernel 2: fold partial chunks; lum_v row-major, lum_i transposed.
// Also zeroes g_sum / g_cnt (stream-ordered before k_pair).
// grid = (B, 2), block = 576
// ---------------------------------------------------------------------------
__global__ void k_lum_reduce() {
    const int b = blockIdx.x;
    const int t = blockIdx.y;
    const int p = threadIdx.x;

    if (b == 0 && t == 0 && p == 0) { g_sum = 0.0; g_cnt = 0; }

    float s = 0.0f;
#pragma unroll
    for (int c = 0; c < NCHUNK; ++c) s += g_part[t][b][c][p];

    if (t == 0) g_lum_v[b][p]  = s;
    else        g_lum_iT[p][b] = s;
}

// ---------------------------------------------------------------------------
// Kernel 3: pairwise MSE + mask + reduce + FINALIZE. block = i, thread = j.
// mse_sum(i,j) = sv2 + si2 - 2*cross (all p-sums), mse = mse_sum / HW.
// fp32 inner chunks (32 terms) flushed to double accumulators.
// Pair count via __syncthreads_count (integer -> deterministic).
// Last block (ticket) computes the final scalar; no k_final kernel.
// grid = 64, block = 64. NOTE: labels are int32 (JAX x64 disabled).
// ---------------------------------------------------------------------------
__global__ void k_pair(const int* __restrict__ labels,
                       float* __restrict__ out) {
    const int i = blockIdx.x;
    const int j = threadIdx.x;   // 0..63

    __shared__ float  s_lv[HW_];
    __shared__ double s_red[64];

    // cooperative load of lum_v[i] (coalesced)
    for (int p = j; p < HW_; p += 64) s_lv[p] = g_lum_v[i][p];
    __syncthreads();

    // sv2 = sum_p lv^2  (per-thread fp32 partial of 9 terms -> double reduce)
    {
        float pv = 0.0f;
        for (int p = j; p < HW_; p += 64) {
            float v = s_lv[p];
            pv = fmaf(v, v, pv);
        }
        s_red[j] = (double)pv;
    }
    __syncthreads();
    for (int s = 32; s > 0; s >>= 1) {
        if (j < s) s_red[j] += s_red[j + s];
        __syncthreads();
    }
    const double sv2 = s_red[0];
    __syncthreads();

    // cross = sum_p lv*li,  si2 = sum_p li^2  (li reads coalesced via transpose)
    double crossd = 0.0, si2d = 0.0;
    for (int p0 = 0; p0 < HW_; p0 += 32) {
        float cf = 0.0f, sf = 0.0f;
#pragma unroll
        for (int k = 0; k < 32; ++k) {
            int   p  = p0 + k;
            float lv = s_lv[p];
            float li = g_lum_iT[p][j];
            cf = fmaf(lv, li, cf);
            sf = fmaf(li, li, sf);
        }
        crossd += (double)cf;
        si2d   += (double)sf;
    }

    const double mse = (sv2 + si2d - 2.0 * crossd) / (double)HW_;

    const bool m = (labels[i] == labels[j]) && (i != j);
    const int cnt_i = __syncthreads_count(m);   // also a barrier

    s_red[j] = m ? mse : 0.0;
    __syncthreads();
    for (int s = 32; s > 0; s >>= 1) {
        if (j < s) s_red[j] += s_red[j + s];
        __syncthreads();
    }

    if (j == 0) {
        atomicAdd(&g_sum, s_red[0]);
        atomicAdd(&g_cnt, cnt_i);
        __threadfence();
        unsigned t = atomicAdd(&g_ticket, 1u);
        if (t == gridDim.x - 1) {
            // last block: all other blocks' adds are globally visible
            double total = atomicAdd(&g_sum, 0.0);   // atomic read
            int    cnt   = atomicAdd(&g_cnt, 0);
            out[0] = (cnt > 0) ? (float)(total / (double)cnt) : 0.0f;
            g_ticket = 0;                            // reset for next replay
        }
    }
}

extern "C" void kernel_launch(void* const* d_in, const int* in_sizes, int n_in,
                              void* d_out, int out_size) {
    const float* fv     = (const float*)d_in[0];
    const float* fi     = (const float*)d_in[1];
    const int*   labels = (const int*)d_in[2];
    float*       out    = (float*)d_out;

    k_lum_partial<<<dim3(NCHUNK, B_, 2), HW_>>>(fv, fi);
    k_lum_reduce<<<dim3(B_, 2), HW_>>>();
    k_pair<<<B_, 64>>>(labels, out);
}